// round 3
// baseline (speedup 1.0000x reference)
#include <cuda_runtime.h>

#define NN 100000
#define NE 400000
#define NG 1000
#define EPSV 1e-5f

__device__ float g_P[(size_t)NN * 256];
__device__ float g_Q[(size_t)NN * 256];
__device__ float g_h1[(size_t)NN * 128];
__device__ float g_h2[(size_t)NN * 256];
__device__ float g_h3[(size_t)NN * 256];
__device__ float g_e0[(size_t)NE * 256];
__device__ float g_e1[(size_t)NE * 128];
__device__ int   g_src[NE];
__device__ int   g_dst[NE];
__device__ int   g_batch[NN];
__device__ float g_deg[NN];
__device__ float g_invdeg[NN];
__device__ double g_sum[256];
__device__ double g_sumsq[256];
__device__ float g_alpha[256];
__device__ float g_beta[256];
__device__ float g_wd[256 * 256];
__device__ float g_pool[NG * 256];
__device__ float g_cnt[NG];
__device__ int   g_is64;

__global__ void k_flag_init() { g_is64 = 1; }

__global__ void k_flag_check(const unsigned long long* __restrict__ e) {
    int i = blockIdx.x * blockDim.x + threadIdx.x;
    for (; i < NE; i += gridDim.x * blockDim.x)
        if (e[i] >= (unsigned long long)NN) g_is64 = 0;
}

__global__ void k_convert(const void* __restrict__ ei, const void* __restrict__ bt) {
    int i0 = blockIdx.x * blockDim.x + threadIdx.x;
    int st = gridDim.x * blockDim.x;
    int is64 = g_is64;
    for (int k = i0; k < NE; k += st) {
        int s, d;
        if (is64) {
            const long long* e = (const long long*)ei;
            s = (int)e[k]; d = (int)e[NE + k];
        } else {
            const int* e = (const int*)ei;
            s = e[k]; d = e[NE + k];
        }
        g_src[k] = s; g_dst[k] = d;
    }
    for (int k = i0; k < NN; k += st)
        g_batch[k] = is64 ? (int)((const long long*)bt)[k] : ((const int*)bt)[k];
}

__global__ void k_deg() {
    int i = blockIdx.x * blockDim.x + threadIdx.x;
    for (; i < NE; i += gridDim.x * blockDim.x) atomicAdd(&g_deg[g_dst[i]], 1.f);
}
__global__ void k_invdeg() {
    int i = blockIdx.x * blockDim.x + threadIdx.x;
    if (i < NN) g_invdeg[i] = 1.f / fmaxf(g_deg[i], 1.f);
}

// layer-1 of block 1: x[N,5] -> P = x@(Wtop-Wbot), Q = x@Wbot  [N,128]
__global__ void k_l1(const float* __restrict__ x, const float* __restrict__ W,
                     float* __restrict__ P, float* __restrict__ Qo) {
    __shared__ float wd[5 * 128], wb[5 * 128];
    int c = threadIdx.x;  // 128
#pragma unroll
    for (int k = 0; k < 5; k++) {
        float t = W[(5 + k) * 128 + c];
        wb[k * 128 + c] = t;
        wd[k * 128 + c] = W[k * 128 + c] - t;
    }
    __syncthreads();
    for (int n = blockIdx.x; n < NN; n += gridDim.x) {
        float xv[5];
#pragma unroll
        for (int k = 0; k < 5; k++) xv[k] = x[n * 5 + k];
        float p = 0.f, q = 0.f;
#pragma unroll
        for (int k = 0; k < 5; k++) {
            p = fmaf(xv[k], wd[k * 128 + c], p);
            q = fmaf(xv[k], wb[k * 128 + c], q);
        }
        P[(size_t)n * 128 + c] = p;
        Qo[(size_t)n * 128 + c] = q;
    }
}

// per-channel stats of h_e = P[dst]+Q[src]+b over edges
__global__ void k_pqstats(const float* __restrict__ P, const float* __restrict__ Qb,
                          const float* __restrict__ comb, int C) {
    int c = threadIdx.x;  // blockDim == C
    float bc = comb[c];
    float s = 0.f, q = 0.f;
    for (int e = blockIdx.x; e < NE; e += gridDim.x) {
        float v = P[(size_t)g_dst[e] * C + c] + Qb[(size_t)g_src[e] * C + c] + bc;
        s += v;
        q = fmaf(v, v, q);
    }
    atomicAdd(&g_sum[c], (double)s);
    atomicAdd(&g_sumsq[c], (double)q);
}

// GraphNorm -> per-channel affine (alpha,beta); resets accumulators
__global__ void k_finalize(const float* __restrict__ gn, int C) {
    int c = threadIdx.x;
    if (c < C) {
        float invE = 1.f / (float)NE;
        float m  = (float)(g_sum[c] * invE);
        float m2 = (float)(g_sumsq[c] * invE);
        float g = gn[c], b = gn[C + c], ms = gn[2 * C + c];
        float var = m2 - 2.f * ms * m * m + ms * ms * m * m;
        float rs = rsqrtf(var + EPSV);
        g_alpha[c] = g * rs;
        g_beta[c]  = b - g * rs * ms * m;
        g_sum[c] = 0.0;
        g_sumsq[c] = 0.0;
    }
}

__device__ __forceinline__ float afr(float v, int k) {
    return fmaxf(fmaf(g_alpha[k], v, g_beta[k]), 0.f);
}

// C[M,N] = f(A)@W + bias. MODE 0: plain A. MODE 1: relu(affine(A)).
// MODE 2: relu(affine(P[dst]+Q[src]+comb)). STATS: accumulate channel sums of C.
template <int MODE, bool STATS>
__global__ void __launch_bounds__(256)
k_gemm(const float* __restrict__ A, const float* __restrict__ Qb,
       const float* __restrict__ W, const float* __restrict__ bias,
       const float* __restrict__ comb, float* __restrict__ Co,
       int M, int K, int N) {
    __shared__ float As[128 * 33];
    __shared__ float Bs[32 * 128];
    const int tid = threadIdx.x;
    const int tx = tid & 15, ty = tid >> 4;
    const int m0 = blockIdx.x * 128, n0 = blockIdx.y * 128;
    float acc[8][8];
#pragma unroll
    for (int i = 0; i < 8; i++)
#pragma unroll
        for (int j = 0; j < 8; j++) acc[i][j] = 0.f;

    const int arow = tid >> 3;
    const int acol = (tid & 7) << 2;
    const int brow = tid >> 5;
    const int bcol = (tid & 31) << 2;

    for (int k0 = 0; k0 < K; k0 += 32) {
#pragma unroll
        for (int p = 0; p < 4; p++) {
            int r = p * 32 + arow;
            int gm = m0 + r;
            float v0 = 0.f, v1 = 0.f, v2 = 0.f, v3 = 0.f;
            if (gm < M) {
                int kg = k0 + acol;
                if (MODE == 0) {
                    float4 t = *(const float4*)(A + (size_t)gm * K + kg);
                    v0 = t.x; v1 = t.y; v2 = t.z; v3 = t.w;
                } else if (MODE == 1) {
                    float4 t = *(const float4*)(A + (size_t)gm * K + kg);
                    v0 = afr(t.x, kg); v1 = afr(t.y, kg + 1);
                    v2 = afr(t.z, kg + 2); v3 = afr(t.w, kg + 3);
                } else {
                    int d = g_dst[gm], s = g_src[gm];
                    float4 pv = *(const float4*)(A + (size_t)d * K + kg);
                    float4 qv = *(const float4*)(Qb + (size_t)s * K + kg);
                    v0 = afr(pv.x + qv.x + comb[kg], kg);
                    v1 = afr(pv.y + qv.y + comb[kg + 1], kg + 1);
                    v2 = afr(pv.z + qv.z + comb[kg + 2], kg + 2);
                    v3 = afr(pv.w + qv.w + comb[kg + 3], kg + 3);
                }
            }
            float* as = As + r * 33 + acol;
            as[0] = v0; as[1] = v1; as[2] = v2; as[3] = v3;
        }
#pragma unroll
        for (int p = 0; p < 4; p++) {
            int kk = p * 8 + brow;
            float4 w = *(const float4*)(W + (size_t)(k0 + kk) * N + n0 + bcol);
            *(float4*)(Bs + kk * 128 + bcol) = w;
        }
        __syncthreads();
#pragma unroll
        for (int kk = 0; kk < 32; kk++) {
            float a[8], b[8];
#pragma unroll
            for (int i = 0; i < 8; i++) a[i] = As[(ty * 8 + i) * 33 + kk];
            float4 b0 = *(const float4*)(Bs + kk * 128 + tx * 8);
            float4 b1 = *(const float4*)(Bs + kk * 128 + tx * 8 + 4);
            b[0] = b0.x; b[1] = b0.y; b[2] = b0.z; b[3] = b0.w;
            b[4] = b1.x; b[5] = b1.y; b[6] = b1.z; b[7] = b1.w;
#pragma unroll
            for (int i = 0; i < 8; i++)
#pragma unroll
                for (int j = 0; j < 8; j++) acc[i][j] = fmaf(a[i], b[j], acc[i][j]);
        }
        __syncthreads();
    }
    float bj[8];
#pragma unroll
    for (int j = 0; j < 8; j++) bj[j] = bias ? bias[n0 + tx * 8 + j] : 0.f;
#pragma unroll
    for (int i = 0; i < 8; i++) {
        int gm = m0 + ty * 8 + i;
        if (gm < M) {
#pragma unroll
            for (int j = 0; j < 8; j++) acc[i][j] += bj[j];
            float4 o0 = make_float4(acc[i][0], acc[i][1], acc[i][2], acc[i][3]);
            float4 o1 = make_float4(acc[i][4], acc[i][5], acc[i][6], acc[i][7]);
            *(float4*)(Co + (size_t)gm * N + n0 + tx * 8) = o0;
            *(float4*)(Co + (size_t)gm * N + n0 + tx * 8 + 4) = o1;
        }
    }
    if (STATS) {  // edge GEMMs only: M % 128 == 0, all rows valid
        float* reds = As;
        float* redq = As + 2048;
#pragma unroll
        for (int j = 0; j < 8; j++) {
            float s = 0.f, q = 0.f;
#pragma unroll
            for (int i = 0; i < 8; i++) { float v = acc[i][j]; s += v; q = fmaf(v, v, q); }
            reds[(tx * 8 + j) * 16 + ty] = s;
            redq[(tx * 8 + j) * 16 + ty] = q;
        }
        __syncthreads();
        if (tid < 128) {
            float S = 0.f, Qs = 0.f;
#pragma unroll
            for (int t = 0; t < 16; t++) { S += reds[tid * 16 + t]; Qs += redq[tid * 16 + t]; }
            atomicAdd(&g_sum[n0 + tid], (double)S);
            atomicAdd(&g_sumsq[n0 + tid], (double)Qs);
        }
    }
}

__global__ void k_wdiff(const float* __restrict__ W, int KN) {
    int i = blockIdx.x * blockDim.x + threadIdx.x;
    for (; i < KN; i += gridDim.x * blockDim.x) g_wd[i] = W[i] - W[KN + i];
}

// scatter relu(affine(H)) to dst nodes (sum; scaled to mean later)
__global__ void k_agg_aff(const float* __restrict__ H, float* __restrict__ node, int logC) {
    int Cm = (1 << logC) - 1;
    size_t tot = (size_t)NE << logC;
    for (size_t idx = (size_t)blockIdx.x * blockDim.x + threadIdx.x; idx < tot;
         idx += (size_t)gridDim.x * blockDim.x) {
        int e = (int)(idx >> logC);
        int c = (int)(idx & Cm);
        float v = fmaxf(fmaf(g_alpha[c], H[idx], g_beta[c]), 0.f);
        atomicAdd(node + ((size_t)g_dst[e] << logC) + c, v);
    }
}

// scatter relu(affine(P[dst]+Q[src]+comb)) to dst (block-3 path, no edge GEMM)
__global__ void k_agg_pq(const float* __restrict__ P, const float* __restrict__ Qb,
                         const float* __restrict__ comb, float* __restrict__ node, int logC) {
    int Cm = (1 << logC) - 1;
    size_t tot = (size_t)NE << logC;
    for (size_t idx = (size_t)blockIdx.x * blockDim.x + threadIdx.x; idx < tot;
         idx += (size_t)gridDim.x * blockDim.x) {
        int e = (int)(idx >> logC);
        int c = (int)(idx & Cm);
        int d = g_dst[e], s = g_src[e];
        float v = P[((size_t)d << logC) + c] + Qb[((size_t)s << logC) + c] + comb[c];
        v = fmaxf(fmaf(g_alpha[c], v, g_beta[c]), 0.f);
        atomicAdd(node + ((size_t)d << logC) + c, v);
    }
}

__global__ void k_scale(float* __restrict__ node, int logC) {
    size_t tot = (size_t)NN << logC;
    for (size_t idx = (size_t)blockIdx.x * blockDim.x + threadIdx.x; idx < tot;
         idx += (size_t)gridDim.x * blockDim.x)
        node[idx] *= g_invdeg[idx >> logC];
}

__global__ void k_pool(const float* __restrict__ h) {
    size_t tot = (size_t)NN * 256;
    for (size_t idx = (size_t)blockIdx.x * blockDim.x + threadIdx.x; idx < tot;
         idx += (size_t)gridDim.x * blockDim.x) {
        int n = (int)(idx >> 8);
        int c = (int)(idx & 255);
        int b = g_batch[n];
        atomicAdd(&g_pool[b * 256 + c], h[idx]);
        if (c == 0) atomicAdd(&g_cnt[b], 1.f);
    }
}

__global__ void k_head(const float* __restrict__ W1, const float* __restrict__ b1,
                       const float* __restrict__ W2, const float* __restrict__ b2,
                       float* __restrict__ out) {
    __shared__ float gv[256], hid[256], r0[256], r1[256];
    int r = blockIdx.x, t = threadIdx.x;
    float cnt = fmaxf(g_cnt[r], 1.f);
    gv[t] = g_pool[r * 256 + t] / cnt;
    __syncthreads();
    float a = b1[t];
    for (int k = 0; k < 256; k++) a = fmaf(gv[k], W1[k * 256 + t], a);
    hid[t] = fmaxf(a, 0.f);
    __syncthreads();
    r0[t] = hid[t] * W2[t * 2 + 0];
    r1[t] = hid[t] * W2[t * 2 + 1];
    __syncthreads();
    for (int s = 128; s > 0; s >>= 1) {
        if (t < s) { r0[t] += r0[t + s]; r1[t] += r1[t + s]; }
        __syncthreads();
    }
    if (t == 0) {
        out[r * 2 + 0] = r0[0] + b2[0];
        out[r * 2 + 1] = r1[0] + b2[1];
    }
}

extern "C" void kernel_launch(void* const* d_in, const int* in_sizes, int n_in,
                              void* d_out, int out_size) {
    const float* x      = (const float*)d_in[0];
    const void*  ei     = d_in[1];
    const void*  bt     = d_in[2];
    const float* c1_w1  = (const float*)d_in[3];
    const float* c1_b1  = (const float*)d_in[4];
    const float* c1_gn1 = (const float*)d_in[5];
    const float* c1_w2  = (const float*)d_in[6];
    const float* c1_b2  = (const float*)d_in[7];
    const float* c1_gn2 = (const float*)d_in[8];
    const float* c1_w3  = (const float*)d_in[9];
    const float* c1_b3  = (const float*)d_in[10];
    const float* c1_gn3 = (const float*)d_in[11];
    const float* c2_w1  = (const float*)d_in[12];
    const float* c2_b1  = (const float*)d_in[13];
    const float* c2_gn1 = (const float*)d_in[14];
    const float* c2_w2  = (const float*)d_in[15];
    const float* c2_b2  = (const float*)d_in[16];
    const float* c2_gn2 = (const float*)d_in[17];
    const float* c3_w1  = (const float*)d_in[18];
    const float* c3_b1  = (const float*)d_in[19];
    const float* c3_gn1 = (const float*)d_in[20];
    const float* lw1    = (const float*)d_in[21];
    const float* lb1    = (const float*)d_in[22];
    const float* lw2    = (const float*)d_in[23];
    const float* lb2    = (const float*)d_in[24];
    float* out = (float*)d_out;
    (void)in_sizes; (void)n_in; (void)out_size;

    float *pP, *pQ, *ph1, *ph2, *ph3, *pe0, *pe1, *pwd, *pdeg, *ppool, *pcnt;
    double *psum, *psq;
    cudaGetSymbolAddress((void**)&pP, g_P);
    cudaGetSymbolAddress((void**)&pQ, g_Q);
    cudaGetSymbolAddress((void**)&ph1, g_h1);
    cudaGetSymbolAddress((void**)&ph2, g_h2);
    cudaGetSymbolAddress((void**)&ph3, g_h3);
    cudaGetSymbolAddress((void**)&pe0, g_e0);
    cudaGetSymbolAddress((void**)&pe1, g_e1);
    cudaGetSymbolAddress((void**)&pwd, g_wd);
    cudaGetSymbolAddress((void**)&pdeg, g_deg);
    cudaGetSymbolAddress((void**)&ppool, g_pool);
    cudaGetSymbolAddress((void**)&pcnt, g_cnt);
    cudaGetSymbolAddress((void**)&psum, g_sum);
    cudaGetSymbolAddress((void**)&psq, g_sumsq);

    // setup
    k_flag_init<<<1, 1>>>();
    k_flag_check<<<512, 256>>>((const unsigned long long*)ei);
    k_convert<<<1024, 256>>>(ei, bt);
    cudaMemsetAsync(pdeg, 0, NN * sizeof(float));
    k_deg<<<1024, 256>>>();
    k_invdeg<<<(NN + 255) / 256, 256>>>();
    cudaMemsetAsync(psum, 0, 256 * sizeof(double));
    cudaMemsetAsync(psq, 0, 256 * sizeof(double));

    // block 1 (C=128, 3 layers)
    k_l1<<<2048, 128>>>(x, c1_w1, pP, pQ);
    k_pqstats<<<2048, 128>>>(pP, pQ, c1_b1, 128);
    k_finalize<<<1, 256>>>(c1_gn1, 128);
    k_gemm<2, true><<<dim3(NE / 128, 1), 256>>>(pP, pQ, c1_w2, c1_b2, c1_b1, pe0, NE, 128, 128);
    k_finalize<<<1, 256>>>(c1_gn2, 128);
    k_gemm<1, true><<<dim3(NE / 128, 1), 256>>>(pe0, nullptr, c1_w3, c1_b3, nullptr, pe1, NE, 128, 128);
    k_finalize<<<1, 256>>>(c1_gn3, 128);
    cudaMemsetAsync(ph1, 0, (size_t)NN * 128 * sizeof(float));
    k_agg_aff<<<16384, 256>>>(pe1, ph1, 7);
    k_scale<<<4096, 256>>>(ph1, 7);

    // block 2 (C=256, 2 layers)
    k_wdiff<<<256, 256>>>(c2_w1, 128 * 256);
    k_gemm<0, false><<<dim3((NN + 127) / 128, 2), 256>>>(ph1, nullptr, pwd, nullptr, nullptr, pP, NN, 128, 256);
    k_gemm<0, false><<<dim3((NN + 127) / 128, 2), 256>>>(ph1, nullptr, c2_w1 + 128 * 256, nullptr, nullptr, pQ, NN, 128, 256);
    k_pqstats<<<2048, 256>>>(pP, pQ, c2_b1, 256);
    k_finalize<<<1, 256>>>(c2_gn1, 256);
    k_gemm<2, true><<<dim3(NE / 128, 2), 256>>>(pP, pQ, c2_w2, c2_b2, c2_b1, pe0, NE, 256, 256);
    k_finalize<<<1, 256>>>(c2_gn2, 256);
    cudaMemsetAsync(ph2, 0, (size_t)NN * 256 * sizeof(float));
    k_agg_aff<<<16384, 256>>>(pe0, ph2, 8);
    k_scale<<<8192, 256>>>(ph2, 8);

    // block 3 (C=256, 1 layer — no edge GEMM needed)
    k_wdiff<<<256, 256>>>(c3_w1, 256 * 256);
    k_gemm<0, false><<<dim3((NN + 127) / 128, 2), 256>>>(ph2, nullptr, pwd, nullptr, nullptr, pP, NN, 256, 256);
    k_gemm<0, false><<<dim3((NN + 127) / 128, 2), 256>>>(ph2, nullptr, c3_w1 + 256 * 256, nullptr, nullptr, pQ, NN, 256, 256);
    k_pqstats<<<2048, 256>>>(pP, pQ, c3_b1, 256);
    k_finalize<<<1, 256>>>(c3_gn1, 256);
    cudaMemsetAsync(ph3, 0, (size_t)NN * 256 * sizeof(float));
    k_agg_pq<<<16384, 256>>>(pP, pQ, c3_b1, ph3, 8);
    k_scale<<<8192, 256>>>(ph3, 8);

    // pool + head
    cudaMemsetAsync(ppool, 0, NG * 256 * sizeof(float));
    cudaMemsetAsync(pcnt, 0, NG * sizeof(float));
    k_pool<<<16384, 256>>>(ph3);
    k_head<<<NG, 256>>>(lw1, lb1, lw2, lb2, out);
}